// round 9
// baseline (speedup 1.0000x reference)
#include <cuda_runtime.h>

#define N_COLS 65536
#define BATCH   256
#define ROWS_PER_BLOCK 8
#define THREADS 256
#define ROW_OCTS (2 * N_COLS / 8)   // x-octs per row = 16384 (also out float4s per row)

// Precomputed per-column coefficients {c0,c1,c2,c3} (1 MiB), indexed by column.
__device__ float4 g_wc[N_COLS];

// W16_TO_4 exactly as the reference builds it (W[3,1] written twice -> final 1).
__constant__ float c_W[4][16] = {
    { 0, 0, 0, 0,  0, 0, 0, 0,   1,  1,  1,  1,   1,  1,  1,  1},
    { 0, 0, 1, 1,  0, 0, 1, 1,  -1, -1,  0,  0,  -1, -1,  0,  0},
    { 0, 0, 0, 0,  1, 1, 1, 1,  -1, -1, -1, -1,   0,  0,  0,  0},
    { 0, 1,-1, 0, -1, 0,-2,-1,   1,  2,  0,  1,   0,  1, -1,  0}
};

struct f8 { float4 lo, hi; };

// 256-bit x load with L2 evict-last (the only form ptxas accepts the hint on).
// x (~128 MiB) nearly fits L2 (~126 MB) and is re-read every replay.
__device__ __forceinline__ f8 ldg_el8(const float* p) {
    unsigned r0, r1, r2, r3, r4, r5, r6, r7;
    asm volatile("ld.global.nc.L2::evict_last.v8.b32 {%0,%1,%2,%3,%4,%5,%6,%7}, [%8];"
                 : "=r"(r0), "=r"(r1), "=r"(r2), "=r"(r3),
                   "=r"(r4), "=r"(r5), "=r"(r6), "=r"(r7)
                 : "l"(p));
    f8 v;
    v.lo.x = __uint_as_float(r0); v.lo.y = __uint_as_float(r1);
    v.lo.z = __uint_as_float(r2); v.lo.w = __uint_as_float(r3);
    v.hi.x = __uint_as_float(r4); v.hi.y = __uint_as_float(r5);
    v.hi.z = __uint_as_float(r6); v.hi.w = __uint_as_float(r7);
    return v;
}

// Kernel 1: per-column softmax over 16 logits + 4x16 projection.
__global__ void wc_precompute_kernel(const float* __restrict__ w) {
    int n = blockIdx.x * blockDim.x + threadIdx.x;

    float v[16];
    float m = -1e30f;
#pragma unroll
    for (int k = 0; k < 16; k++) {
        v[k] = __ldg(&w[k * N_COLS + n]);
        m = fmaxf(m, v[k]);
    }
    float s = 0.0f;
#pragma unroll
    for (int k = 0; k < 16; k++) {
        v[k] = __expf(v[k] - m);
        s += v[k];
    }
    float inv = 1.0f / s;

    float c0 = 0.f, c1 = 0.f, c2 = 0.f, c3 = 0.f;
#pragma unroll
    for (int k = 0; k < 16; k++) {
        c0 = fmaf(c_W[0][k], v[k], c0);
        c1 = fmaf(c_W[1][k], v[k], c1);
        c2 = fmaf(c_W[2][k], v[k], c2);
        c3 = fmaf(c_W[3][k], v[k], c3);
    }
    g_wc[n] = make_float4(c0 * inv, c1 * inv, c2 * inv, c3 * inv);
}

// Kernel 2: streaming bilinear gate, oct-per-thread layout.
// Thread t owns x-oct o = blk*256 + t (8 floats = columns 4o..4o+3):
//   per row: 1x LDG.256 evict-last (warp: 1024B contiguous)
//            1x STG.128 evict-first (warp: 512B contiguous)
// Coefficients for the 4 columns live in registers across 8 rows.
// 4-row load batches keep 128B/thread in flight.
__global__ void __launch_bounds__(THREADS, 4)
gate_apply_kernel(const float* __restrict__ x, float4* __restrict__ out) {
    const int o  = blockIdx.x * THREADS + threadIdx.x;   // oct index in row
    const int b0 = blockIdx.y * ROWS_PER_BLOCK;

    // Coefficients for columns 4o .. 4o+3
    const float4 w0 = g_wc[4 * o + 0];
    const float4 w1 = g_wc[4 * o + 1];
    const float4 w2 = g_wc[4 * o + 2];
    const float4 w3 = g_wc[4 * o + 3];

    const float* xp = x + (size_t)b0 * (8 * ROW_OCTS) + (size_t)o * 8;
    float4*      op = out + (size_t)b0 * ROW_OCTS + o;

#pragma unroll
    for (int h = 0; h < ROWS_PER_BLOCK / 4; h++) {
        f8 a[4];
#pragma unroll
        for (int i = 0; i < 4; i++)
            a[i] = ldg_el8(xp + (size_t)i * (8 * ROW_OCTS));
#pragma unroll
        for (int i = 0; i < 4; i++) {
            float4 r;
            // out = c0 + c1*A + c2*B + c3*A*B = fma(A, fma(B,c3,c1), fma(B,c2,c0))
            r.x = fmaf(a[i].lo.x, fmaf(a[i].lo.y, w0.w, w0.y), fmaf(a[i].lo.y, w0.z, w0.x));
            r.y = fmaf(a[i].lo.z, fmaf(a[i].lo.w, w1.w, w1.y), fmaf(a[i].lo.w, w1.z, w1.x));
            r.z = fmaf(a[i].hi.x, fmaf(a[i].hi.y, w2.w, w2.y), fmaf(a[i].hi.y, w2.z, w2.x));
            r.w = fmaf(a[i].hi.z, fmaf(a[i].hi.w, w3.w, w3.y), fmaf(a[i].hi.w, w3.z, w3.x));
            __stcs(op + (size_t)i * ROW_OCTS, r);        // evict-first STG.128
        }
        xp += (size_t)4 * (8 * ROW_OCTS);
        op += (size_t)4 * ROW_OCTS;
    }
}

extern "C" void kernel_launch(void* const* d_in, const int* in_sizes, int n_in,
                              void* d_out, int out_size) {
    const float* x = (const float*)d_in[0];   // (256, 131072)
    const float* w = (const float*)d_in[1];   // (16, 65536)
    float* out = (float*)d_out;               // (256, 65536)

    wc_precompute_kernel<<<N_COLS / 256, 256>>>(w);

    dim3 grid(ROW_OCTS / THREADS, BATCH / ROWS_PER_BLOCK);  // (64, 32)
    gate_apply_kernel<<<grid, THREADS>>>(x, (float4*)out);
}